// round 6
// baseline (speedup 1.0000x reference)
#include <cuda_runtime.h>
#include <cstdint>

// Problem constants (from reference):
//   B=256, P=4096, H=W=512
// Inputs (metadata order):
//   d_in[0]: indices   int32  [B, P, 2]   (JAX x64 disabled: jnp.int64 request -> int32)
//   d_in[1]: num_valid int32  [B]
//   d_in[2]: feats     float32[B, P, 1]
// Output: float32 [B, H, W]

#define B_ 256
#define P_ 4096
#define H_ 512
#define W_ 512

#define THREADS_    512
#define PTS_PER_T   (P_ / THREADS_)             // 8 prefetched points per thread
#define SMEM_BYTES  32768                       // 32 KB zero buffer
#define SLICE_BYTES (H_ * W_ * 4)               // 1 MB per batch
#define N_CHUNKS    (SLICE_BYTES / SMEM_BYTES)  // 32 bulk stores per batch

__device__ __forceinline__ uint32_t smem_u32(const void* p) {
    uint32_t a;
    asm("{ .reg .u64 t; cvta.to.shared.u64 t, %1; cvt.u32.u64 %0, t; }"
        : "=r"(a) : "l"(p));
    return a;
}

__global__ __launch_bounds__(THREADS_, 2)
void scatter_densify_tma2_kernel(const int* __restrict__ indices,
                                 const int* __restrict__ num_valid,
                                 const float* __restrict__ feats,
                                 float* __restrict__ out)
{
    __shared__ __align__(128) float4 zbuf[SMEM_BYTES / 16];

    const int b = blockIdx.x;
    float* slice = out + (size_t)b * (H_ * W_);
    const int nv = num_valid[b];

    // ---- Prefetch scatter operands (overlaps with everything below) ----
    const int2*  ib = reinterpret_cast<const int2*>(indices) + (size_t)b * P_;
    const float* fb = feats + (size_t)b * P_;

    int2  rc[PTS_PER_T];
    float fv[PTS_PER_T];
    #pragma unroll
    for (int k = 0; k < PTS_PER_T; k++) {
        const int p = threadIdx.x + k * THREADS_;
        if (p < nv) {
            rc[k] = ib[p];
            fv[k] = fb[p];
        }
    }

    // ---- Phase 1a: zero the 32 KB SMEM staging buffer (4 iterations) ----
    const float4 z = make_float4(0.f, 0.f, 0.f, 0.f);
    #pragma unroll
    for (int i = threadIdx.x; i < SMEM_BYTES / 16; i += THREADS_) {
        zbuf[i] = z;
    }
    __syncthreads();

    // ---- Phase 1b: TMA bulk-store zeros over this batch's 1 MB slice ----
    if (threadIdx.x == 0) {
        asm volatile("fence.proxy.async.shared::cta;" ::: "memory");
        const uint32_t src = smem_u32(zbuf);
        char* dst = reinterpret_cast<char*>(slice);
        #pragma unroll
        for (int c = 0; c < N_CHUNKS; c++) {
            asm volatile(
                "cp.async.bulk.global.shared::cta.bulk_group [%0], [%1], %2;"
                :: "l"(dst + (size_t)c * SMEM_BYTES), "r"(src), "n"(SMEM_BYTES)
                : "memory");
        }
        asm volatile("cp.async.bulk.commit_group;" ::: "memory");
        asm volatile("cp.async.bulk.wait_group 0;" ::: "memory");
    }
    __syncthreads();   // zero-fill visible to all threads

    // ---- Phase 2: scatter-add prefetched points (pure RED issue) ----
    #pragma unroll
    for (int k = 0; k < PTS_PER_T; k++) {
        const int p = threadIdx.x + k * THREADS_;
        if (p < nv) {
            const int r = rc[k].x;
            const int c = rc[k].y;
            if ((unsigned)r < H_ && (unsigned)c < W_) {
                atomicAdd(slice + r * W_ + c, fv[k]);
            }
        }
    }
}

extern "C" void kernel_launch(void* const* d_in, const int* in_sizes, int n_in,
                              void* d_out, int out_size)
{
    const int*   indices = (const int*)d_in[0];
    const int*   nvalid  = (const int*)d_in[1];
    const float* feats   = (const float*)d_in[2];
    float*       out     = (float*)d_out;

    scatter_densify_tma2_kernel<<<B_, THREADS_>>>(indices, nvalid, feats, out);
}

// round 7
// speedup vs baseline: 1.0043x; 1.0043x over previous
#include <cuda_runtime.h>
#include <cstdint>

// Problem constants (from reference):
//   B=256, P=4096, H=W=512
// Inputs (metadata order):
//   d_in[0]: indices   int32  [B, P, 2]   (JAX x64 disabled: jnp.int64 request -> int32)
//   d_in[1]: num_valid int32  [B]
//   d_in[2]: feats     float32[B, P, 1]
// Output: float32 [B, H, W]

#define B_ 256
#define P_ 4096
#define H_ 512
#define W_ 512

#define SCAT_THREADS_ 256
#define N_POINTS_     (B_ * P_)     // 1,048,576

__global__ __launch_bounds__(SCAT_THREADS_)
void scatter_only_kernel(const int* __restrict__ indices,
                         const int* __restrict__ num_valid,
                         const float* __restrict__ feats,
                         float* __restrict__ out)
{
    const int i = blockIdx.x * SCAT_THREADS_ + threadIdx.x;   // flat point id
    const int b = i >> 12;          // batch  (P_ = 4096)
    const int p = i & (P_ - 1);     // point within batch

    const int nv = __ldg(num_valid + b);    // broadcast within each block half
    if (p < nv) {
        const int2 rc = reinterpret_cast<const int2*>(indices)[i];
        const int r = rc.x;
        const int c = rc.y;
        if ((unsigned)r < H_ && (unsigned)c < W_) {
            const float v = __ldg(feats + i);
            atomicAdd(out + (size_t)b * (H_ * W_) + r * W_ + c, v);
        }
    }
}

extern "C" void kernel_launch(void* const* d_in, const int* in_sizes, int n_in,
                              void* d_out, int out_size)
{
    const int*   indices = (const int*)d_in[0];
    const int*   nvalid  = (const int*)d_in[1];
    const float* feats   = (const float*)d_in[2];
    float*       out     = (float*)d_out;

    // Driver-optimal zero fill of the full [B, H, W] output (graph memset node).
    cudaMemsetAsync(d_out, 0, (size_t)out_size * sizeof(float));

    // Flat scatter: one thread per (batch, point).
    scatter_only_kernel<<<N_POINTS_ / SCAT_THREADS_, SCAT_THREADS_>>>(
        indices, nvalid, feats, out);
}